// round 17
// baseline (speedup 1.0000x reference)
#include <cuda_runtime.h>
#include <cuda_bf16.h>
#include <cuda_fp16.h>
#include <math.h>
#include <stdint.h>

#define T_SEQ  2048
#define HIDDEN 4096
#define NH     32
#define NKV    8
#define HD     128
#define Q_SIZE  (NH * HD)              // 4096
#define KV_SIZE (NKV * HD)             // 1024
#define QKV_N   (Q_SIZE + 2 * KV_SIZE) // 6144
#define SCALE   0.08838834764831845f   // 128^-0.5

// ---------------------------------------------------------------------------
// Global scratch. No cudaMalloc allowed.
// ---------------------------------------------------------------------------
__device__ uint32_t g_hid[(size_t)T_SEQ * HIDDEN / 2];         // fp16
__device__ uint32_t g_wqkv[(size_t)HIDDEN * QKV_N / 2];        // fp16
__device__ uint32_t g_wo[(size_t)HIDDEN * HIDDEN / 2];         // fp16
__device__ uint32_t g_qf[(size_t)T_SEQ * Q_SIZE / 2];          // fp16 Q
__device__ uint32_t g_kf[(size_t)T_SEQ * KV_SIZE / 2];         // fp16 K
__device__ uint32_t g_vf[(size_t)T_SEQ * KV_SIZE / 2];         // fp16 V
__device__ uint32_t g_ao[(size_t)T_SEQ * Q_SIZE / 2];          // fp16 attn out
__device__ float2   g_rope[(size_t)T_SEQ * 64];                // (cos,sin)

// ---------------------------------------------------------------------------
// Helpers
// ---------------------------------------------------------------------------
__device__ __forceinline__ uint32_t smem_u32(const void* p) {
    uint32_t a;
    asm("{ .reg .u64 t; cvta.to.shared.u64 t, %1; cvt.u32.u64 %0, t; }"
        : "=r"(a) : "l"(p));
    return a;
}
// fp16 MMA (everything)
__device__ __forceinline__ void mma16h(float* c, const uint32_t* a,
                                       const uint32_t* b) {
    asm volatile(
        "mma.sync.aligned.m16n8k16.row.col.f32.f16.f16.f32 "
        "{%0,%1,%2,%3}, {%4,%5,%6,%7}, {%8,%9}, {%0,%1,%2,%3};"
        : "+f"(c[0]), "+f"(c[1]), "+f"(c[2]), "+f"(c[3])
        : "r"(a[0]), "r"(a[1]), "r"(a[2]), "r"(a[3]), "r"(b[0]), "r"(b[1]));
}
__device__ __forceinline__ void ldmx4(uint32_t* r, uint32_t addr) {
    asm volatile(
        "ldmatrix.sync.aligned.m8n8.x4.shared.b16 {%0,%1,%2,%3}, [%4];"
        : "=r"(r[0]), "=r"(r[1]), "=r"(r[2]), "=r"(r[3]) : "r"(addr));
}
__device__ __forceinline__ void ldmx4t(uint32_t* r, uint32_t addr) {
    asm volatile(
        "ldmatrix.sync.aligned.m8n8.x4.trans.shared.b16 {%0,%1,%2,%3}, [%4];"
        : "=r"(r[0]), "=r"(r[1]), "=r"(r[2]), "=r"(r[3]) : "r"(addr));
}
__device__ __forceinline__ void cpa16(uint32_t dst, const void* src) {
    asm volatile("cp.async.cg.shared.global [%0], [%1], 16;"
                 :: "r"(dst), "l"(src));
}
__device__ __forceinline__ void cpa_commit() {
    asm volatile("cp.async.commit_group;");
}
template <int N>
__device__ __forceinline__ void cpa_wait() {
    asm volatile("cp.async.wait_group %0;" :: "n"(N));
}

// ---------------------------------------------------------------------------
// fp32 -> fp16 (single rounding)
// ---------------------------------------------------------------------------
__global__ __launch_bounds__(256) void convert_h(
    const float4* __restrict__ src, uint2* __restrict__ dh, int n4)
{
    for (int i = blockIdx.x * blockDim.x + threadIdx.x; i < n4;
         i += gridDim.x * blockDim.x) {
        float4 v = src[i];
        __half2 a = __floats2half2_rn(v.x, v.y);
        __half2 b = __floats2half2_rn(v.z, v.w);
        dh[i] = make_uint2(*(uint32_t*)&a, *(uint32_t*)&b);
    }
}

// ---------------------------------------------------------------------------
// RoPE cos/sin table
// ---------------------------------------------------------------------------
__global__ __launch_bounds__(256) void rope_table_kernel(
    const int* __restrict__ positions, float2* __restrict__ tab)
{
    const int idx = blockIdx.x * blockDim.x + threadIdx.x;
    if (idx >= T_SEQ * 64) return;
    const int t = idx >> 6;
    const int i = idx & 63;
    double e = (double)(2 * i) / (double)HD;
    float invf = (float)pow(500000.0, -e);
    float s, c;
    sincosf((float)positions[t] * invf, &s, &c);
    tab[idx] = make_float2(c, s);
}

// ===========================================================================
// FP16 GEMM core: CTA tile 128(M) x 64(N), BK=64, 128 threads (4 warps,
// 2x2 grid, warp tile 64x32), 3-stage cp.async, one barrier per kt.
// Smaller N-tile halves the CTA drain tail (2x CTAs, half tile time).
// ===========================================================================
#define GBK 64
#define AST 72                  // A row stride (elems): 64 + 8 pad
#define BSTN 72                 // B k-row stride (elems): 64 + 8 pad
#define STG_B   (128 * AST)     // 9216 elems
#define STG_ELEMS (128 * AST + GBK * BSTN)  // 13824 elems = 27648 B
#define NSTG 3

__global__ __launch_bounds__(128, 2) void gemm_qkv_fused(
    const __half* __restrict__ A, const __half* __restrict__ B,
    const float2* __restrict__ rope_tab,
    uint32_t* __restrict__ qf, uint32_t* __restrict__ kf,
    uint32_t* __restrict__ vf)
{
    extern __shared__ __align__(16) __half sm[];
    const uint32_t smb = smem_u32(sm);

    const int tid  = threadIdx.x;
    const int wid  = tid >> 5;
    const int lane = tid & 31;
    const int g    = lane >> 2;
    const int tg   = lane & 3;
    const int wm   = (wid >> 1) * 64;
    const int wn   = (wid & 1) * 32;
    const int m0 = blockIdx.y * 128;
    const int n0 = blockIdx.x * 64;
    const int K = HIDDEN, N = QKV_N;

    const int l7  = lane & 7;
    const int l8  = (lane >> 3) & 1;
    const int l16 = lane >> 4;
    const uint32_t aFrag = (uint32_t)(((wm + l7 + l8 * 8) * AST + l16 * 8) * 2);
    const uint32_t bFrag = (uint32_t)(STG_B * 2) +
        (uint32_t)(((l7 + l8 * 8) * BSTN + wn + l16 * 8) * 2);

    float acc[4][4][4];
    #pragma unroll
    for (int i = 0; i < 4; i++)
        #pragma unroll
        for (int j = 0; j < 4; j++)
            #pragma unroll
            for (int q = 0; q < 4; q++) acc[i][j][q] = 0.f;

    const int KT = K / GBK;

    auto issue = [&](int kt, int s) {
        const int kk = kt * GBK;
        const uint32_t sb = smb + (uint32_t)(s * STG_ELEMS * 2);
        #pragma unroll
        for (int i = 0; i < 8; i++) {
            const int c = tid + i * 128;
            const int row = c >> 3, c8 = (c & 7) * 8;
            cpa16(sb + (row * AST + c8) * 2,
                  A + (size_t)(m0 + row) * K + kk + c8);
        }
        #pragma unroll
        for (int i = 0; i < 4; i++) {
            const int c = tid + i * 128;
            const int row = c >> 3, c8 = (c & 7) * 8;
            cpa16(sb + (STG_B + row * BSTN + c8) * 2,
                  B + (size_t)(kk + row) * N + n0 + c8);
        }
    };

    issue(0, 0); cpa_commit();
    issue(1, 1); cpa_commit();

    int stage = 0;
    for (int kt = 0; kt < KT; kt++) {
        cpa_wait<1>();
        __syncthreads();

        if (kt + 2 < KT) {
            int s2 = stage + 2; if (s2 >= NSTG) s2 -= NSTG;
            issue(kt + 2, s2);
        }
        cpa_commit();

        const uint32_t sb = smb + (uint32_t)(stage * STG_ELEMS * 2);
        const uint32_t aA = sb + aFrag;
        const uint32_t bA = sb + bFrag;

        uint32_t aF[2][4][4];
        #pragma unroll
        for (int mt = 0; mt < 4; mt++)
            ldmx4(aF[0][mt], aA + mt * (16 * AST * 2));

        #pragma unroll
        for (int ks = 0; ks < 4; ks++) {
            const int cur = ks & 1;
            uint32_t bh[2][4];
            #pragma unroll
            for (int pp = 0; pp < 2; pp++)
                ldmx4t(bh[pp], bA + ks * (16 * BSTN * 2) + pp * 32);
            if (ks < 3) {
                #pragma unroll
                for (int mt = 0; mt < 4; mt++)
                    ldmx4(aF[cur ^ 1][mt],
                          aA + mt * (16 * AST * 2) + (ks + 1) * 32);
            }
            #pragma unroll
            for (int mt = 0; mt < 4; mt++)
                #pragma unroll
                for (int nt = 0; nt < 4; nt++)
                    mma16h(acc[mt][nt], aF[cur][mt],
                           &bh[nt >> 1][(nt & 1) * 2]);
        }
        if (++stage == NSTG) stage = 0;
    }

    // ---- fused epilogue: table-driven rope + fp16 stores ----
    const int region = (n0 >= Q_SIZE + KV_SIZE) ? 2 : (n0 >= Q_SIZE ? 1 : 0);

    #pragma unroll
    for (int mt = 0; mt < 4; mt++) {
        const int rowA = m0 + wm + mt * 16 + g;
        const int rowB = rowA + 8;
        #pragma unroll
        for (int nt = 0; nt < 4; nt++) {
            const int col = n0 + wn + nt * 8 + tg * 2;
            const float x0a = acc[mt][nt][0], x1a = acc[mt][nt][1];
            const float x0b = acc[mt][nt][2], x1b = acc[mt][nt][3];
            if (region == 2) {
                const int c = col - (Q_SIZE + KV_SIZE);
                __half2 h0 = __floats2half2_rn(x0a, x1a);
                vf[((size_t)rowA * KV_SIZE + c) >> 1] = *(uint32_t*)&h0;
                __half2 h1 = __floats2half2_rn(x0b, x1b);
                vf[((size_t)rowB * KV_SIZE + c) >> 1] = *(uint32_t*)&h1;
            } else {
                const int fi = (col >> 1) & 63;
                const float2 ta = rope_tab[rowA * 64 + fi];
                const float2 tb = rope_tab[rowB * 64 + fi];
                float o1 = x0a * ta.x - x1a * ta.y;
                float o2 = x1a * ta.x + x0a * ta.y;
                float o3 = x0b * tb.x - x1b * tb.y;
                float o4 = x1b * tb.x + x0b * tb.y;
                if (region == 0) {
                    __half2 h0 = __floats2half2_rn(o1 * SCALE, o2 * SCALE);
                    qf[((size_t)rowA * Q_SIZE + col) >> 1] = *(uint32_t*)&h0;
                    __half2 h1 = __floats2half2_rn(o3 * SCALE, o4 * SCALE);
                    qf[((size_t)rowB * Q_SIZE + col) >> 1] = *(uint32_t*)&h1;
                } else {
                    const int c = col - Q_SIZE;
                    __half2 h0 = __floats2half2_rn(o1, o2);
                    kf[((size_t)rowA * KV_SIZE + c) >> 1] = *(uint32_t*)&h0;
                    __half2 h1 = __floats2half2_rn(o3, o4);
                    kf[((size_t)rowB * KV_SIZE + c) >> 1] = *(uint32_t*)&h1;
                }
            }
        }
    }
}

// ---------------------------------------------------------------------------
// Plain FP16 GEMM (O-projection), 128x64 tiles, fp32 out.
// ---------------------------------------------------------------------------
__global__ __launch_bounds__(128, 2) void gemm_fp16(
    const __half* __restrict__ A, const __half* __restrict__ B,
    float* __restrict__ C, int M, int N, int K)
{
    extern __shared__ __align__(16) __half sm[];
    const uint32_t smb = smem_u32(sm);

    const int tid  = threadIdx.x;
    const int wid  = tid >> 5;
    const int lane = tid & 31;
    const int g    = lane >> 2;
    const int tg   = lane & 3;
    const int wm   = (wid >> 1) * 64;
    const int wn   = (wid & 1) * 32;
    const int m0 = blockIdx.y * 128;
    const int n0 = blockIdx.x * 64;

    const int l7  = lane & 7;
    const int l8  = (lane >> 3) & 1;
    const int l16 = lane >> 4;
    const uint32_t aFrag = (uint32_t)(((wm + l7 + l8 * 8) * AST + l16 * 8) * 2);
    const uint32_t bFrag = (uint32_t)(STG_B * 2) +
        (uint32_t)(((l7 + l8 * 8) * BSTN + wn + l16 * 8) * 2);

    float acc[4][4][4];
    #pragma unroll
    for (int i = 0; i < 4; i++)
        #pragma unroll
        for (int j = 0; j < 4; j++)
            #pragma unroll
            for (int q = 0; q < 4; q++) acc[i][j][q] = 0.f;

    const int KT = K / GBK;

    auto issue = [&](int kt, int s) {
        const int kk = kt * GBK;
        const uint32_t sb = smb + (uint32_t)(s * STG_ELEMS * 2);
        #pragma unroll
        for (int i = 0; i < 8; i++) {
            const int c = tid + i * 128;
            const int row = c >> 3, c8 = (c & 7) * 8;
            cpa16(sb + (row * AST + c8) * 2,
                  A + (size_t)(m0 + row) * K + kk + c8);
        }
        #pragma unroll
        for (int i = 0; i < 4; i++) {
            const int c = tid + i * 128;
            const int row = c >> 3, c8 = (c & 7) * 8;
            cpa16(sb + (STG_B + row * BSTN + c8) * 2,
                  B + (size_t)(kk + row) * N + n0 + c8);
        }
    };

    issue(0, 0); cpa_commit();
    issue(1, 1); cpa_commit();

    int stage = 0;
    for (int kt = 0; kt < KT; kt++) {
        cpa_wait<1>();
        __syncthreads();

        if (kt + 2 < KT) {
            int s2 = stage + 2; if (s2 >= NSTG) s2 -= NSTG;
            issue(kt + 2, s2);
        }
        cpa_commit();

        const uint32_t sb = smb + (uint32_t)(stage * STG_ELEMS * 2);
        const uint32_t aA = sb + aFrag;
        const uint32_t bA = sb + bFrag;

        uint32_t aF[2][4][4];
        #pragma unroll
        for (int mt = 0; mt < 4; mt++)
            ldmx4(aF[0][mt], aA + mt * (16 * AST * 2));

        #pragma unroll
        for (int ks = 0; ks < 4; ks++) {
            const int cur = ks & 1;
            uint32_t bh[2][4];
            #pragma unroll
            for (int pp = 0; pp < 2; pp++)
                ldmx4t(bh[pp], bA + ks * (16 * BSTN * 2) + pp * 32);
            if (ks < 3) {
                #pragma unroll
                for (int mt = 0; mt < 4; mt++)
                    ldmx4(aF[cur ^ 1][mt],
                          aA + mt * (16 * AST * 2) + (ks + 1) * 32);
            }
            #pragma unroll
            for (int mt = 0; mt < 4; mt++)
                #pragma unroll
                for (int nt = 0; nt < 4; nt++)
                    mma16h(acc[mt][nt], aF[cur][mt],
                           &bh[nt >> 1][(nt & 1) * 2]);
        }
        if (++stage == NSTG) stage = 0;
    }

    #pragma unroll
    for (int mt = 0; mt < 4; mt++) {
        const int row = m0 + wm + mt * 16 + g;
        #pragma unroll
        for (int nt = 0; nt < 4; nt++) {
            const int col = n0 + wn + nt * 8 + tg * 2;
            *(float2*)&C[(size_t)row * N + col] =
                make_float2(acc[mt][nt][0], acc[mt][nt][1]);
            *(float2*)&C[(size_t)(row + 8) * N + col] =
                make_float2(acc[mt][nt][2], acc[mt][nt][3]);
        }
    }
}

// ---------------------------------------------------------------------------
// Tensor-core causal GQA flash attention — all fp16, 1-term S and PV.
// ---------------------------------------------------------------------------
#define FBM 128
#define FBN 64
#define KVST 136
#define KVB_E   17408                   // Q only
#define KV_STG  17408                   // per stage: Kf, Vf
#define SV      8704
#define ATT_SMEM_BYTES ((KVB_E + 2 * KV_STG) * 2)   // 104448

__global__ __launch_bounds__(256, 1) void attn_tc2_kernel(
    const __half* __restrict__ Qf,
    const __half* __restrict__ Kf, const __half* __restrict__ Vf,
    uint32_t* __restrict__ Oo)
{
    extern __shared__ __align__(16) __half asmem[];
    const uint32_t smb = smem_u32(asmem);

    const int tid  = threadIdx.x;
    const int wid  = tid >> 5;
    const int lane = tid & 31;
    const int g    = lane >> 2;
    const int tg   = lane & 3;
    const int mt   = (gridDim.x - 1) - blockIdx.x;
    const int m0   = mt * FBM;
    const int h    = blockIdx.y;
    const int kh   = h >> 2;

    const int l7  = lane & 7;
    const int l8  = (lane >> 3) & 1;
    const int l16 = lane >> 4;

    const int lr = tid >> 4;
    const int lc = tid & 15;

    #pragma unroll
    for (int i = 0; i < 8; i++) {
        const int row = lr + i * 16;
        const size_t go = (size_t)(m0 + row) * Q_SIZE + h * HD + lc * 8;
        cpa16(smb + (row * KVST + lc * 8) * 2, Qf + go);
    }
    cpa_commit();

    auto issueKV = [&](int j0, int s) {
        const uint32_t sb = smb + (uint32_t)((KVB_E + s * KV_STG) * 2);
        #pragma unroll
        for (int i = 0; i < 4; i++) {
            const int row = lr + i * 16;
            const size_t go = (size_t)(j0 + row) * KV_SIZE + kh * HD + lc * 8;
            const uint32_t so = (row * KVST + lc * 8) * 2;
            cpa16(sb + so, Kf + go);
            cpa16(sb + SV * 2 + so, Vf + go);
        }
    };

    issueKV(0, 0);
    cpa_commit();

    float o[16][4];
    #pragma unroll
    for (int n = 0; n < 16; n++)
        #pragma unroll
        for (int q = 0; q < 4; q++) o[n][q] = 0.f;
    float m_0 = -1e30f, m_1 = -1e30f, l_0 = 0.f, l_1 = 0.f;

    const uint32_t qFrag =
        (uint32_t)(((wid * 16 + l7 + l8 * 8) * KVST + l16 * 8) * 2);
    const uint32_t kFrag =
        (uint32_t)(((l7 + l16 * 8) * KVST + l8 * 8) * 2);
    const uint32_t vFrag =
        (uint32_t)(((l7 + l8 * 8) * KVST + l16 * 8) * 2);

    const int ntiles = m0 / FBN + 2;

    for (int jt = 0; jt < ntiles; jt++) {
        if (jt + 1 < ntiles) issueKV((jt + 1) * FBN, (jt + 1) & 1);
        cpa_commit();
        cpa_wait<1>();
        __syncthreads();

        const int j0 = jt * FBN;
        const uint32_t sb = smb + (uint32_t)((KVB_E + (jt & 1) * KV_STG) * 2);
        const uint32_t kB = sb + kFrag;
        const uint32_t vB = sb + SV * 2 + vFrag;

        float s[8][4];
        #pragma unroll
        for (int n = 0; n < 8; n++)
            #pragma unroll
            for (int q = 0; q < 4; q++) s[n][q] = 0.f;

        #pragma unroll
        for (int kt = 0; kt < 8; kt++) {
            uint32_t ah[4];
            ldmx4(ah, smb + qFrag + kt * 32);
            #pragma unroll
            for (int p = 0; p < 4; p++) {
                uint32_t bh[4];
                ldmx4(bh, kB + p * (16 * KVST * 2) + kt * 32);
                mma16h(s[2 * p],     ah, &bh[0]);
                mma16h(s[2 * p + 1], ah, &bh[2]);
            }
        }

        const int row0 = m0 + wid * 16 + g;
        const int row1 = row0 + 8;
        if (j0 + FBN - 1 > row0) {
            #pragma unroll
            for (int n = 0; n < 8; n++) {
                int col = j0 + n * 8 + 2 * tg;
                if (col     > row0) s[n][0] = -1e30f;
                if (col + 1 > row0) s[n][1] = -1e30f;
                if (col     > row1) s[n][2] = -1e30f;
                if (col + 1 > row1) s[n][3] = -1e30f;
            }
        }

        float rmax0 = -1e30f, rmax1 = -1e30f;
        #pragma unroll
        for (int n = 0; n < 8; n++) {
            rmax0 = fmaxf(rmax0, fmaxf(s[n][0], s[n][1]));
            rmax1 = fmaxf(rmax1, fmaxf(s[n][2], s[n][3]));
        }
        rmax0 = fmaxf(rmax0, __shfl_xor_sync(0xffffffffu, rmax0, 1));
        rmax0 = fmaxf(rmax0, __shfl_xor_sync(0xffffffffu, rmax0, 2));
        rmax1 = fmaxf(rmax1, __shfl_xor_sync(0xffffffffu, rmax1, 1));
        rmax1 = fmaxf(rmax1, __shfl_xor_sync(0xffffffffu, rmax1, 2));

        float mn0 = fmaxf(m_0, rmax0), mn1 = fmaxf(m_1, rmax1);
        float f0 = __expf(m_0 - mn0), f1 = __expf(m_1 - mn1);
        m_0 = mn0; m_1 = mn1;

        float rs0 = 0.f, rs1 = 0.f;
        #pragma unroll
        for (int n = 0; n < 8; n++) {
            s[n][0] = __expf(s[n][0] - mn0);
            s[n][1] = __expf(s[n][1] - mn0);
            s[n][2] = __expf(s[n][2] - mn1);
            s[n][3] = __expf(s[n][3] - mn1);
            rs0 += s[n][0] + s[n][1];
            rs1 += s[n][2] + s[n][3];
        }
        rs0 += __shfl_xor_sync(0xffffffffu, rs0, 1);
        rs0 += __shfl_xor_sync(0xffffffffu, rs0, 2);
        rs1 += __shfl_xor_sync(0xffffffffu, rs1, 1);
        rs1 += __shfl_xor_sync(0xffffffffu, rs1, 2);
        l_0 = l_0 * f0 + rs0;
        l_1 = l_1 * f1 + rs1;

        #pragma unroll
        for (int n = 0; n < 16; n++) {
            o[n][0] *= f0; o[n][1] *= f0;
            o[n][2] *= f1; o[n][3] *= f1;
        }

        // O += P V  (1-term fp16)
        #pragma unroll
        for (int kt = 0; kt < 4; kt++) {
            uint32_t ph[4];
            __half2 t;
            t = __floats2half2_rn(s[2 * kt][0],     s[2 * kt][1]);
            ph[0] = *(uint32_t*)&t;
            t = __floats2half2_rn(s[2 * kt][2],     s[2 * kt][3]);
            ph[1] = *(uint32_t*)&t;
            t = __floats2half2_rn(s[2 * kt + 1][0], s[2 * kt + 1][1]);
            ph[2] = *(uint32_t*)&t;
            t = __floats2half2_rn(s[2 * kt + 1][2], s[2 * kt + 1][3]);
            ph[3] = *(uint32_t*)&t;
            #pragma unroll
            for (int p = 0; p < 8; p++) {
                uint32_t bh[4];
                const uint32_t va = vB + kt * (16 * KVST * 2) + p * 32;
                ldmx4t(bh, va);
                mma16h(o[2 * p],     ph, &bh[0]);
                mma16h(o[2 * p + 1], ph, &bh[2]);
            }
        }
        __syncthreads();
    }

    // epilogue: single fp16 output for the O-projection
    const float il0 = 1.0f / l_0;
    const float il1 = 1.0f / l_1;
    const int row0 = m0 + wid * 16 + g;
    #pragma unroll
    for (int n = 0; n < 16; n++) {
        const int col = n * 8 + 2 * tg;
        __half2 h0 = __floats2half2_rn(o[n][0] * il0, o[n][1] * il0);
        Oo[((size_t)row0 * Q_SIZE + h * HD + col) >> 1] = *(uint32_t*)&h0;
        __half2 h1 = __floats2half2_rn(o[n][2] * il1, o[n][3] * il1);
        Oo[((size_t)(row0 + 8) * Q_SIZE + h * HD + col) >> 1] = *(uint32_t*)&h1;
    }
}

// ---------------------------------------------------------------------------
extern "C" void kernel_launch(void* const* d_in, const int* in_sizes, int n_in,
                              void* d_out, int out_size)
{
    const int*   positions = (const int*)d_in[0];
    const float* hidden    = (const float*)d_in[1];
    const float* w_qkv     = (const float*)d_in[2];
    const float* w_o       = (const float*)d_in[3];
    float* out = (float*)d_out;

    uint32_t *hid, *wqkv, *wo;
    uint32_t *qf, *kf, *vf, *ao;
    float2* rope_tab;
    cudaGetSymbolAddress((void**)&hid,  g_hid);
    cudaGetSymbolAddress((void**)&wqkv, g_wqkv);
    cudaGetSymbolAddress((void**)&wo,   g_wo);
    cudaGetSymbolAddress((void**)&qf, g_qf);
    cudaGetSymbolAddress((void**)&kf, g_kf);
    cudaGetSymbolAddress((void**)&vf, g_vf);
    cudaGetSymbolAddress((void**)&ao, g_ao);
    cudaGetSymbolAddress((void**)&rope_tab, g_rope);

    const int GSM = NSTG * STG_ELEMS * 2;   // 82944
    cudaFuncSetAttribute(gemm_qkv_fused,
                         cudaFuncAttributeMaxDynamicSharedMemorySize, GSM);
    cudaFuncSetAttribute(gemm_fp16,
                         cudaFuncAttributeMaxDynamicSharedMemorySize, GSM);
    cudaFuncSetAttribute(attn_tc2_kernel,
                         cudaFuncAttributeMaxDynamicSharedMemorySize,
                         ATT_SMEM_BYTES);

    // 0) conversions + rope table
    rope_table_kernel<<<(T_SEQ * 64 + 255) / 256, 256>>>(positions, rope_tab);
    convert_h<<<2048, 256>>>((const float4*)hidden, (uint2*)hid,
                             T_SEQ * HIDDEN / 4);
    convert_h<<<4096, 256>>>((const float4*)w_qkv, (uint2*)wqkv,
                             HIDDEN * QKV_N / 4);
    convert_h<<<4096, 256>>>((const float4*)w_o, (uint2*)wo,
                             HIDDEN * HIDDEN / 4);

    // 1) QKV projection with fused (table-driven) RoPE epilogue
    gemm_qkv_fused<<<dim3(QKV_N / 64, T_SEQ / 128), 128, GSM>>>(
        (const __half*)hid, (const __half*)wqkv, rope_tab,
        qf, kf, vf);

    // 2) Flash attention (1-term fp16 S and PV)
    attn_tc2_kernel<<<dim3(T_SEQ / FBM, NH), 256, ATT_SMEM_BYTES>>>(
        (const __half*)qf, (const __half*)kf, (const __half*)vf,
        ao);

    // 3) Output projection (fp16)
    gemm_fp16<<<dim3(HIDDEN / 64, T_SEQ / 128), 128, GSM>>>(
        (const __half*)ao, (const __half*)wo, out, T_SEQ, HIDDEN, HIDDEN);
}